// round 2
// baseline (speedup 1.0000x reference)
#include <cuda_runtime.h>
#include <cuda_bf16.h>
#include <cstdint>

#define NN 50000
#define EEDGES 800000

// ---------------- scratch (device globals, no allocation) ----------------
__device__ float g_xs1[NN * 256];
__device__ float g_h[NN * 256];
__device__ float g_acc1[NN * 256];
__device__ float g_as1[NN * 8];
__device__ float g_ad1[NN * 8];
__device__ float g_mx1[NN * 8];
__device__ float g_dn1[NN * 8];
__device__ float g_xs2[NN * 64];
__device__ float g_acc2[NN * 64];
__device__ float g_as2[NN];
__device__ float g_ad2[NN];
__device__ float g_mx2[NN];
__device__ float g_dn2[NN];
__device__ int   g_is64;

// ---------------- helpers ----------------
__device__ __forceinline__ void atomicMaxF(float* addr, float v) {
    if (v >= 0.0f) {
        atomicMax((int*)addr, __float_as_int(v));
    } else {
        atomicMin((unsigned int*)addr, __float_as_uint(v));
    }
}

__device__ __forceinline__ void load_edge(const void* ei, int e, int E, int& s, int& d) {
    if (g_is64) {
        const long long* p = (const long long*)ei;
        s = (int)p[e];
        d = (int)p[E + e];
    } else {
        const int* p = (const int*)ei;
        s = p[e];
        d = p[E + e];
    }
}

__device__ __forceinline__ float lrelu(float a) { return a > 0.0f ? a : 0.2f * a; }

// ---------------- dtype detection for edge_index ----------------
__global__ void k_set_flag() { g_is64 = 1; }

__global__ void k_detect(const int* e32, int E) {
    int i = blockIdx.x * blockDim.x + threadIdx.x;
    if (i < E) {
        // int64 little-endian values < 2^31 have zero high words at all odd int32 slots
        if (e32[2 * i + 1] != 0) g_is64 = 0;
    }
}

// ---------------- fp32 tiled GEMM: C[M,N] = A[M,K] @ B[K,N] ----------------
// 64x64 block tile, BK=16, 256 threads, 4x4 per thread. K % 16 == 0, N % 64 == 0.
__global__ void k_sgemm(const float* __restrict__ A, const float* __restrict__ B,
                        float* __restrict__ C, int M, int N, int K) {
    __shared__ float As[16][68];
    __shared__ float Bs[16][64];
    int tid = threadIdx.x;
    int tx = tid & 15, ty = tid >> 4;
    int row0 = blockIdx.y * 64, col0 = blockIdx.x * 64;

    int am = tid >> 2;         // 0..63
    int ak = (tid & 3) * 4;    // 0,4,8,12
    int bk = tid >> 4;         // 0..15
    int bn = (tid & 15) * 4;   // 0..60

    float acc[4][4] = {};
    for (int k0 = 0; k0 < K; k0 += 16) {
        float4 av = make_float4(0.f, 0.f, 0.f, 0.f);
        int gm = row0 + am;
        if (gm < M) av = *(const float4*)&A[(size_t)gm * K + k0 + ak];
        As[ak + 0][am] = av.x;
        As[ak + 1][am] = av.y;
        As[ak + 2][am] = av.z;
        As[ak + 3][am] = av.w;
        float4 bv = *(const float4*)&B[(size_t)(k0 + bk) * N + col0 + bn];
        *(float4*)&Bs[bk][bn] = bv;
        __syncthreads();
#pragma unroll
        for (int k = 0; k < 16; k++) {
            float a[4], b[4];
#pragma unroll
            for (int i = 0; i < 4; i++) a[i] = As[k][ty * 4 + i];
#pragma unroll
            for (int j = 0; j < 4; j++) b[j] = Bs[k][tx * 4 + j];
#pragma unroll
            for (int i = 0; i < 4; i++)
#pragma unroll
                for (int j = 0; j < 4; j++) acc[i][j] += a[i] * b[j];
        }
        __syncthreads();
    }
#pragma unroll
    for (int i = 0; i < 4; i++) {
        int gm = row0 + ty * 4 + i;
        if (gm < M)
            *(float4*)&C[(size_t)gm * N + col0 + tx * 4] =
                make_float4(acc[i][0], acc[i][1], acc[i][2], acc[i][3]);
    }
}

// ---------------- attention scores: a_src / a_dst per (node,head) ----------------
__global__ void k_scores(const float* __restrict__ xs, const float* __restrict__ atts,
                         const float* __restrict__ attd, float* __restrict__ as_,
                         float* __restrict__ ad_, int NH, int H, int C) {
    int i = blockIdx.x * blockDim.x + threadIdx.x;
    if (i >= NH) return;
    int h = (H == 1) ? 0 : (i % H);
    const float* xr = xs + (size_t)i * C;
    const float* sr = atts + h * C;
    const float* dr = attd + h * C;
    float ss = 0.f, dd = 0.f;
    for (int c = 0; c < C; c += 4) {
        float4 xv = *(const float4*)&xr[c];
        float4 sv = *(const float4*)&sr[c];
        float4 dv = *(const float4*)&dr[c];
        ss += xv.x * sv.x + xv.y * sv.y + xv.z * sv.z + xv.w * sv.w;
        dd += xv.x * dv.x + xv.y * dv.y + xv.z * dv.z + xv.w * dv.w;
    }
    as_[i] = ss;
    ad_[i] = dd;
}

// init max with the self-loop score
__global__ void k_init_max(const float* __restrict__ as_, const float* __restrict__ ad_,
                           float* __restrict__ mx, int NH) {
    int i = blockIdx.x * blockDim.x + threadIdx.x;
    if (i >= NH) return;
    mx[i] = lrelu(as_[i] + ad_[i]);
}

// per-edge segment max
__global__ void k_edge_max(const void* __restrict__ ei, int E, const float* __restrict__ as_,
                           const float* __restrict__ ad_, float* __restrict__ mx, int H) {
    int e = blockIdx.x * blockDim.x + threadIdx.x;
    if (e >= E) return;
    int s, d;
    load_edge(ei, e, E, s, d);
    for (int h = 0; h < H; h++) {
        float a = lrelu(as_[s * H + h] + ad_[d * H + h]);
        atomicMaxF(&mx[d * H + h], a);
    }
}

// node init: denom = exp(self - max); acc = exp_self * xs (self-loop contribution)
__global__ void k_node_init(const float* __restrict__ as_, const float* __restrict__ ad_,
                            const float* __restrict__ mx, float* __restrict__ den,
                            const float* __restrict__ xs, float* __restrict__ acc,
                            int NH, int C) {
    int i = blockIdx.x * blockDim.x + threadIdx.x;
    if (i >= NH) return;
    float a = lrelu(as_[i] + ad_[i]);
    float ex = expf(a - mx[i]);
    den[i] = ex;
    const float* xr = xs + (size_t)i * C;
    float* ar = acc + (size_t)i * C;
    for (int c = 0; c < C; c += 4) {
        float4 v = *(const float4*)&xr[c];
        *(float4*)&ar[c] = make_float4(v.x * ex, v.y * ex, v.z * ex, v.w * ex);
    }
}

__device__ __forceinline__ void red_add_v4(float* p, float4 v) {
    asm volatile("red.global.add.v4.f32 [%0], {%1,%2,%3,%4};"
                 :: "l"(p), "f"(v.x), "f"(v.y), "f"(v.z), "f"(v.w)
                 : "memory");
}

// layer 1 aggregate: warp per edge, H=8, C=32 (256 floats scatter per edge)
__global__ void k_edge_agg1(const void* __restrict__ ei, int E, const float* __restrict__ as_,
                            const float* __restrict__ ad_, const float* __restrict__ mx,
                            float* __restrict__ den, const float* __restrict__ xs,
                            float* __restrict__ acc) {
    int gw = (blockIdx.x * blockDim.x + threadIdx.x) >> 5;
    int lane = threadIdx.x & 31;
    if (gw >= E) return;
    int s, d;
    load_edge(ei, gw, E, s, d);
    float ex = 0.f;
    if (lane < 8) {
        float a = lrelu(as_[s * 8 + lane] + ad_[d * 8 + lane]);
        ex = expf(a - mx[d * 8 + lane]);
        atomicAdd(&den[d * 8 + lane], ex);
    }
    int h4 = lane >> 3;          // 0..3
    int c4 = (lane & 7) * 4;     // 0..28
#pragma unroll
    for (int j = 0; j < 2; j++) {
        int head = j * 4 + h4;
        float exh = __shfl_sync(0xffffffffu, ex, head);
        float4 v = *(const float4*)&xs[((size_t)s * 8 + head) * 32 + c4];
        red_add_v4(&acc[((size_t)d * 8 + head) * 32 + c4],
                   make_float4(v.x * exh, v.y * exh, v.z * exh, v.w * exh));
    }
}

// layer 2 aggregate: warp per edge, H=1, C=64
__global__ void k_edge_agg2(const void* __restrict__ ei, int E, const float* __restrict__ as_,
                            const float* __restrict__ ad_, const float* __restrict__ mx,
                            float* __restrict__ den, const float* __restrict__ xs,
                            float* __restrict__ acc) {
    int gw = (blockIdx.x * blockDim.x + threadIdx.x) >> 5;
    int lane = threadIdx.x & 31;
    if (gw >= E) return;
    int s, d;
    load_edge(ei, gw, E, s, d);
    float ex = 0.f;
    if (lane == 0) {
        float a = lrelu(as_[s] + ad_[d]);
        ex = expf(a - mx[d]);
        atomicAdd(&den[d], ex);
    }
    ex = __shfl_sync(0xffffffffu, ex, 0);
    if (lane < 16) {
        float4 v = *(const float4*)&xs[(size_t)s * 64 + lane * 4];
        red_add_v4(&acc[(size_t)d * 64 + lane * 4],
                   make_float4(v.x * ex, v.y * ex, v.z * ex, v.w * ex));
    }
}

// finalize layer 1: h = elu(acc/den + bias), layout [n, h*32+c] (256 per node)
__global__ void k_fin1(const float* __restrict__ acc, const float* __restrict__ den,
                       const float* __restrict__ bias, float* __restrict__ h, int total) {
    int i = blockIdx.x * blockDim.x + threadIdx.x;
    if (i >= total) return;
    int nh = i >> 5;  // (n*8+h)
    float v = acc[i] / den[nh] + bias[i & 255];
    h[i] = v > 0.f ? v : (expf(v) - 1.0f);
}

// finalize layer 2: out = acc/den + bias
__global__ void k_fin2(const float* __restrict__ acc, const float* __restrict__ den,
                       const float* __restrict__ bias, float* __restrict__ out, int total) {
    int i = blockIdx.x * blockDim.x + threadIdx.x;
    if (i >= total) return;
    int n = i >> 6;
    out[i] = acc[i] / den[n] + bias[i & 63];
}

// ---------------- launcher ----------------
extern "C" void kernel_launch(void* const* d_in, const int* in_sizes, int n_in,
                              void* d_out, int out_size) {
    const float* x   = (const float*)d_in[0];
    const void*  ei  = d_in[1];
    const float* W1  = (const float*)d_in[2];
    const float* at1s = (const float*)d_in[3];
    const float* at1d = (const float*)d_in[4];
    const float* b1  = (const float*)d_in[5];
    const float* W2  = (const float*)d_in[6];
    const float* at2s = (const float*)d_in[7];
    const float* at2d = (const float*)d_in[8];
    const float* b2  = (const float*)d_in[9];
    float* out = (float*)d_out;

    int Nn = in_sizes[0] / 128;   // 50000
    int E  = in_sizes[1] / 2;     // 800000

    float *xs1, *h, *acc1, *as1, *ad1, *mx1, *dn1;
    float *xs2, *acc2, *as2, *ad2, *mx2, *dn2;
    cudaGetSymbolAddress((void**)&xs1, g_xs1);
    cudaGetSymbolAddress((void**)&h, g_h);
    cudaGetSymbolAddress((void**)&acc1, g_acc1);
    cudaGetSymbolAddress((void**)&as1, g_as1);
    cudaGetSymbolAddress((void**)&ad1, g_ad1);
    cudaGetSymbolAddress((void**)&mx1, g_mx1);
    cudaGetSymbolAddress((void**)&dn1, g_dn1);
    cudaGetSymbolAddress((void**)&xs2, g_xs2);
    cudaGetSymbolAddress((void**)&acc2, g_acc2);
    cudaGetSymbolAddress((void**)&as2, g_as2);
    cudaGetSymbolAddress((void**)&ad2, g_ad2);
    cudaGetSymbolAddress((void**)&mx2, g_mx2);
    cudaGetSymbolAddress((void**)&dn2, g_dn2);

    const int T = 256;

    // dtype detection for edge_index (int64 vs int32)
    k_set_flag<<<1, 1>>>();
    k_detect<<<(E + T - 1) / T, T>>>((const int*)ei, E);

    // ---- Layer 1 (H=8, C=32) ----
    {
        dim3 grid(256 / 64, (Nn + 63) / 64);
        k_sgemm<<<grid, T>>>(x, W1, xs1, Nn, 256, 128);
    }
    k_scores<<<(Nn * 8 + T - 1) / T, T>>>(xs1, at1s, at1d, as1, ad1, Nn * 8, 8, 32);
    k_init_max<<<(Nn * 8 + T - 1) / T, T>>>(as1, ad1, mx1, Nn * 8);
    k_edge_max<<<(E + T - 1) / T, T>>>(ei, E, as1, ad1, mx1, 8);
    k_node_init<<<(Nn * 8 + T - 1) / T, T>>>(as1, ad1, mx1, dn1, xs1, acc1, Nn * 8, 32);
    {
        long long thr = (long long)E * 32;
        k_edge_agg1<<<(unsigned)((thr + T - 1) / T), T>>>(ei, E, as1, ad1, mx1, dn1, xs1, acc1);
    }
    k_fin1<<<(Nn * 256 + T - 1) / T, T>>>(acc1, dn1, b1, h, Nn * 256);

    // ---- Layer 2 (H=1, C=64) ----
    {
        dim3 grid(64 / 64, (Nn + 63) / 64);
        k_sgemm<<<grid, T>>>(h, W2, xs2, Nn, 64, 256);
    }
    k_scores<<<(Nn + T - 1) / T, T>>>(xs2, at2s, at2d, as2, ad2, Nn, 1, 64);
    k_init_max<<<(Nn + T - 1) / T, T>>>(as2, ad2, mx2, Nn);
    k_edge_max<<<(E + T - 1) / T, T>>>(ei, E, as2, ad2, mx2, 1);
    k_node_init<<<(Nn + T - 1) / T, T>>>(as2, ad2, mx2, dn2, xs2, acc2, Nn, 64);
    {
        long long thr = (long long)E * 32;
        k_edge_agg2<<<(unsigned)((thr + T - 1) / T), T>>>(ei, E, as2, ad2, mx2, dn2, xs2, acc2);
    }
    k_fin2<<<(Nn * 64 + T - 1) / T, T>>>(acc2, dn2, b2, out, Nn * 64);
}

// round 3
// speedup vs baseline: 1.4547x; 1.4547x over previous
#include <cuda_runtime.h>
#include <cuda_bf16.h>
#include <cstdint>

#define NN 50000
#define EE 800000

// ---------------- scratch (device globals, no allocation) ----------------
__device__ float g_xs1[NN * 256];
__device__ float g_h[NN * 256];
__device__ float g_xs2[NN * 64];
__device__ float g_as1[NN * 8];
__device__ float g_ad1[NN * 8];
__device__ float g_as2[NN];
__device__ float g_ad2[NN];
__device__ int   g_cnt[NN];
__device__ int   g_ptr[NN + 1];
__device__ int   g_cur[NN];
__device__ int   g_csr[EE];
__device__ float g_Ms1;
__device__ float g_Ms2;
__device__ int   g_is64;

// ---------------- helpers ----------------
__device__ __forceinline__ float lrelu(float a) { return a > 0.0f ? a : 0.2f * a; }

__device__ __forceinline__ void atomicMaxF(float* addr, float v) {
    if (v >= 0.0f) atomicMax((int*)addr, __float_as_int(v));
    else           atomicMin((unsigned int*)addr, __float_as_uint(v));
}

__device__ __forceinline__ void load_edge(const void* ei, int e, int E, int& s, int& d) {
    if (g_is64) {
        const long long* p = (const long long*)ei;
        s = (int)p[e];
        d = (int)p[E + e];
    } else {
        const int* p = (const int*)ei;
        s = p[e];
        d = p[E + e];
    }
}

__device__ __forceinline__ void ffma2(unsigned long long& d,
                                      unsigned long long a, unsigned long long b) {
    asm("fma.rn.f32x2 %0, %1, %2, %0;" : "+l"(d) : "l"(a), "l"(b));
}

// ---------------- init + dtype detect ----------------
__global__ void k_init(int n) {
    int i = blockIdx.x * blockDim.x + threadIdx.x;
    if (i < n) g_cnt[i] = 0;
    if (i == 0) { g_Ms1 = -1e30f; g_Ms2 = -1e30f; g_is64 = 1; }
}

__global__ void k_detect(const int* e32, int E) {
    int i = blockIdx.x * blockDim.x + threadIdx.x;
    if (i < E) { if (e32[2 * i + 1] != 0) g_is64 = 0; }
}

// ---------------- CSR build ----------------
__global__ void k_hist(const void* __restrict__ ei, int E) {
    int e = blockIdx.x * blockDim.x + threadIdx.x;
    if (e >= E) return;
    int s, d; load_edge(ei, e, E, s, d);
    atomicAdd(&g_cnt[d], 1);
}

__global__ void k_scan(int n) {
    __shared__ int wsum[32];
    int tid = threadIdx.x, lane = tid & 31, wid = tid >> 5;
    int carry = 0;
    for (int base = 0; base < n; base += 1024) {
        int i = base + tid;
        int v = (i < n) ? g_cnt[i] : 0;
        int x = v;
#pragma unroll
        for (int o = 1; o < 32; o <<= 1) {
            int t = __shfl_up_sync(0xffffffffu, x, o);
            if (lane >= o) x += t;
        }
        if (lane == 31) wsum[wid] = x;
        __syncthreads();
        if (wid == 0) {
            int w = wsum[lane];
#pragma unroll
            for (int o = 1; o < 32; o <<= 1) {
                int t = __shfl_up_sync(0xffffffffu, w, o);
                if (lane >= o) w += t;
            }
            wsum[lane] = w;
        }
        __syncthreads();
        int wpre = (wid > 0) ? wsum[wid - 1] : 0;
        int excl = x - v + wpre + carry;
        if (i < n) { g_ptr[i] = excl; g_cur[i] = excl; }
        carry += wsum[31];
        __syncthreads();
    }
    if (tid == 0) g_ptr[n] = carry;
}

__global__ void k_scatter(const void* __restrict__ ei, int E) {
    int e = blockIdx.x * blockDim.x + threadIdx.x;
    if (e >= E) return;
    int s, d; load_edge(ei, e, E, s, d);
    int pos = atomicAdd(&g_cur[d], 1);
    g_csr[pos] = s;
}

// ---------------- GEMM: C[M,N] = A[M,K] @ B[K,N] via fma.rn.f32x2 ----------------
// 128x64 block tile, BK=16, 256 threads, 8x4 per thread (4 M-pairs x 4 N).
__global__ void __launch_bounds__(256) k_gemm(const float* __restrict__ A,
                                              const float* __restrict__ B,
                                              float* __restrict__ C,
                                              int M, int N, int K) {
    __shared__ __align__(16) float As[16][128];   // [k][m] transposed
    __shared__ __align__(16) float Bsd[16][128];  // [k][2n] duplicated pairs
    int tid = threadIdx.x;
    int tx = tid & 15, ty = tid >> 4;
    int row0 = blockIdx.y * 128, col0 = blockIdx.x * 64;

    int am = tid >> 1;            // 0..127
    int ak = (tid & 1) * 8;       // 0 or 8
    int bk = tid >> 4;            // 0..15
    int bn = (tid & 15) * 4;      // 0..60

    unsigned long long acc[4][4];
#pragma unroll
    for (int i = 0; i < 4; i++)
#pragma unroll
        for (int j = 0; j < 4; j++) acc[i][j] = 0ull;

    for (int kb = 0; kb < K; kb += 16) {
        float4 a0 = make_float4(0.f, 0.f, 0.f, 0.f), a1 = a0;
        int gr = row0 + am;
        if (gr < M) {
            a0 = *(const float4*)&A[(size_t)gr * K + kb + ak];
            a1 = *(const float4*)&A[(size_t)gr * K + kb + ak + 4];
        }
        As[ak + 0][am] = a0.x; As[ak + 1][am] = a0.y;
        As[ak + 2][am] = a0.z; As[ak + 3][am] = a0.w;
        As[ak + 4][am] = a1.x; As[ak + 5][am] = a1.y;
        As[ak + 6][am] = a1.z; As[ak + 7][am] = a1.w;

        float4 b = *(const float4*)&B[(size_t)(kb + bk) * N + col0 + bn];
        *(float4*)&Bsd[bk][2 * bn]     = make_float4(b.x, b.x, b.y, b.y);
        *(float4*)&Bsd[bk][2 * bn + 4] = make_float4(b.z, b.z, b.w, b.w);
        __syncthreads();

#pragma unroll
        for (int k = 0; k < 16; k++) {
            ulonglong2 pa = *(const ulonglong2*)&As[k][ty * 8];
            ulonglong2 pb = *(const ulonglong2*)&As[k][ty * 8 + 4];
            ulonglong2 qa = *(const ulonglong2*)&Bsd[k][tx * 8];
            ulonglong2 qb = *(const ulonglong2*)&Bsd[k][tx * 8 + 4];
            unsigned long long p[4] = { pa.x, pa.y, pb.x, pb.y };
            unsigned long long q[4] = { qa.x, qa.y, qb.x, qb.y };
#pragma unroll
            for (int i = 0; i < 4; i++)
#pragma unroll
                for (int j = 0; j < 4; j++) ffma2(acc[i][j], p[i], q[j]);
        }
        __syncthreads();
    }

#pragma unroll
    for (int i = 0; i < 4; i++) {
        float2 c[4];
#pragma unroll
        for (int j = 0; j < 4; j++) c[j] = *(float2*)&acc[i][j];
        int r = row0 + ty * 8 + 2 * i;
        if (r < M)
            *(float4*)&C[(size_t)r * N + col0 + tx * 4] =
                make_float4(c[0].x, c[1].x, c[2].x, c[3].x);
        if (r + 1 < M)
            *(float4*)&C[(size_t)(r + 1) * N + col0 + tx * 4] =
                make_float4(c[0].y, c[1].y, c[2].y, c[3].y);
    }
}

// ---------------- scores layer 1: warp per node (H=8, C=32) ----------------
__global__ void k_scores1(const float* __restrict__ xs, const float* __restrict__ atts,
                          const float* __restrict__ attd, float* __restrict__ as_,
                          float* __restrict__ ad_, int n) {
    __shared__ float smax[8];
    int w = (blockIdx.x * blockDim.x + threadIdx.x) >> 5;
    int lane = threadIdx.x & 31;
    int wid = threadIdx.x >> 5;
    float mloc = -1e30f;
    if (w < n) {
        const float* xr = xs + (size_t)w * 256;
        float4 x0 = *(const float4*)&xr[4 * lane];
        float4 x1 = *(const float4*)&xr[128 + 4 * lane];
        float4 s0 = *(const float4*)&atts[4 * lane];
        float4 s1 = *(const float4*)&atts[128 + 4 * lane];
        float4 d0 = *(const float4*)&attd[4 * lane];
        float4 d1 = *(const float4*)&attd[128 + 4 * lane];
        float slo = x0.x * s0.x + x0.y * s0.y + x0.z * s0.z + x0.w * s0.w;
        float shi = x1.x * s1.x + x1.y * s1.y + x1.z * s1.z + x1.w * s1.w;
        float dlo = x0.x * d0.x + x0.y * d0.y + x0.z * d0.z + x0.w * d0.w;
        float dhi = x1.x * d1.x + x1.y * d1.y + x1.z * d1.z + x1.w * d1.w;
#pragma unroll
        for (int o = 1; o < 8; o <<= 1) {
            slo += __shfl_xor_sync(0xffffffffu, slo, o);
            shi += __shfl_xor_sync(0xffffffffu, shi, o);
            dlo += __shfl_xor_sync(0xffffffffu, dlo, o);
            dhi += __shfl_xor_sync(0xffffffffu, dhi, o);
        }
        if ((lane & 7) == 0) {
            int h = lane >> 3;
            as_[w * 8 + h] = slo;
            as_[w * 8 + 4 + h] = shi;
            ad_[w * 8 + h] = dlo;
            ad_[w * 8 + 4 + h] = dhi;
        }
        mloc = fmaxf(slo, shi);
    }
#pragma unroll
    for (int o = 16; o > 0; o >>= 1)
        mloc = fmaxf(mloc, __shfl_xor_sync(0xffffffffu, mloc, o));
    if (lane == 0) smax[wid] = mloc;
    __syncthreads();
    if (threadIdx.x == 0) {
        float m = smax[0];
        for (int i = 1; i < 8; i++) m = fmaxf(m, smax[i]);
        atomicMaxF(&g_Ms1, m);
    }
}

// ---------------- scores layer 2: warp per node (H=1, C=64) ----------------
__global__ void k_scores2(const float* __restrict__ xs, const float* __restrict__ atts,
                          const float* __restrict__ attd, float* __restrict__ as_,
                          float* __restrict__ ad_, int n) {
    __shared__ float smax[8];
    int w = (blockIdx.x * blockDim.x + threadIdx.x) >> 5;
    int lane = threadIdx.x & 31;
    int wid = threadIdx.x >> 5;
    float mloc = -1e30f;
    if (w < n) {
        float ss = 0.f, dd = 0.f;
        if (lane < 16) {
            float4 xv = *(const float4*)&xs[(size_t)w * 64 + 4 * lane];
            float4 sv = *(const float4*)&atts[4 * lane];
            float4 dv = *(const float4*)&attd[4 * lane];
            ss = xv.x * sv.x + xv.y * sv.y + xv.z * sv.z + xv.w * sv.w;
            dd = xv.x * dv.x + xv.y * dv.y + xv.z * dv.z + xv.w * dv.w;
        }
#pragma unroll
        for (int o = 1; o < 16; o <<= 1) {
            ss += __shfl_xor_sync(0xffffffffu, ss, o);
            dd += __shfl_xor_sync(0xffffffffu, dd, o);
        }
        if (lane == 0) { as_[w] = ss; ad_[w] = dd; }
        mloc = ss;
    }
#pragma unroll
    for (int o = 16; o > 0; o >>= 1)
        mloc = fmaxf(mloc, __shfl_xor_sync(0xffffffffu, mloc, o));
    if (lane == 0) smax[wid] = mloc;
    __syncthreads();
    if (threadIdx.x == 0) {
        float m = smax[0];
        for (int i = 1; i < 8; i++) m = fmaxf(m, smax[i]);
        atomicMaxF(&g_Ms2, m);
    }
}

// ---------------- fused aggregate layer 1 (warp per dest, H=8, C=32) ----------------
// softmax (proxy-max shifted) + weighted sum + bias + ELU, all in registers.
__global__ void k_agg1(const float* __restrict__ as_, const float* __restrict__ ad_,
                       const float* __restrict__ xs, const float* __restrict__ bias,
                       float* __restrict__ hout, int n) {
    int w = (blockIdx.x * blockDim.x + threadIdx.x) >> 5;
    int lane = threadIdx.x & 31;
    if (w >= n) return;
    float Ms = g_Ms1;

    float as_h = 0.f, ad_h = 0.f, m = 0.f;
    if (lane < 8) {
        as_h = as_[w * 8 + lane];
        ad_h = ad_[w * 8 + lane];
        m = lrelu(Ms + ad_h);
    }
    float ex = (lane < 8) ? __expf(lrelu(as_h + ad_h) - m) : 0.f;
    float den = ex;

    int hsel = lane >> 3;                    // 0..3
    float elo = __shfl_sync(0xffffffffu, ex, hsel);
    float ehi = __shfl_sync(0xffffffffu, ex, 4 + hsel);

    const float* xr = xs + (size_t)w * 256;
    float4 v0 = *(const float4*)&xr[4 * lane];
    float4 v1 = *(const float4*)&xr[128 + 4 * lane];
    float4 a0 = make_float4(v0.x * elo, v0.y * elo, v0.z * elo, v0.w * elo);
    float4 a1 = make_float4(v1.x * ehi, v1.y * ehi, v1.z * ehi, v1.w * ehi);

    int beg = g_ptr[w], end = g_ptr[w + 1];
    for (int e = beg; e < end; e++) {
        int s = g_csr[e];
        float exh = 0.f;
        if (lane < 8) {
            float a = lrelu(as_[s * 8 + lane] + ad_h);
            exh = __expf(a - m);
            den += exh;
        }
        float flo = __shfl_sync(0xffffffffu, exh, hsel);
        float fhi = __shfl_sync(0xffffffffu, exh, 4 + hsel);
        const float* ur = xs + (size_t)s * 256;
        float4 u0 = *(const float4*)&ur[4 * lane];
        float4 u1 = *(const float4*)&ur[128 + 4 * lane];
        a0.x += u0.x * flo; a0.y += u0.y * flo; a0.z += u0.z * flo; a0.w += u0.w * flo;
        a1.x += u1.x * fhi; a1.y += u1.y * fhi; a1.z += u1.z * fhi; a1.w += u1.w * fhi;
    }

    float dlo = __shfl_sync(0xffffffffu, den, hsel);
    float dhi = __shfl_sync(0xffffffffu, den, 4 + hsel);
    float rlo = 1.0f / dlo, rhi = 1.0f / dhi;
    float4 blo = *(const float4*)&bias[4 * lane];
    float4 bhi = *(const float4*)&bias[128 + 4 * lane];
    float4 o0, o1;
    o0.x = a0.x * rlo + blo.x; o0.y = a0.y * rlo + blo.y;
    o0.z = a0.z * rlo + blo.z; o0.w = a0.w * rlo + blo.w;
    o1.x = a1.x * rhi + bhi.x; o1.y = a1.y * rhi + bhi.y;
    o1.z = a1.z * rhi + bhi.z; o1.w = a1.w * rhi + bhi.w;
    // ELU
    o0.x = o0.x > 0.f ? o0.x : (expf(o0.x) - 1.f);
    o0.y = o0.y > 0.f ? o0.y : (expf(o0.y) - 1.f);
    o0.z = o0.z > 0.f ? o0.z : (expf(o0.z) - 1.f);
    o0.w = o0.w > 0.f ? o0.w : (expf(o0.w) - 1.f);
    o1.x = o1.x > 0.f ? o1.x : (expf(o1.x) - 1.f);
    o1.y = o1.y > 0.f ? o1.y : (expf(o1.y) - 1.f);
    o1.z = o1.z > 0.f ? o1.z : (expf(o1.z) - 1.f);
    o1.w = o1.w > 0.f ? o1.w : (expf(o1.w) - 1.f);
    float* hr = hout + (size_t)w * 256;
    *(float4*)&hr[4 * lane] = o0;
    *(float4*)&hr[128 + 4 * lane] = o1;
}

// ---------------- fused aggregate layer 2 (warp per dest, H=1, C=64) ----------------
__global__ void k_agg2(const float* __restrict__ as_, const float* __restrict__ ad_,
                       const float* __restrict__ xs, const float* __restrict__ bias,
                       float* __restrict__ out, int n) {
    int w = (blockIdx.x * blockDim.x + threadIdx.x) >> 5;
    int lane = threadIdx.x & 31;
    if (w >= n) return;
    float Ms = g_Ms2;
    float adv = ad_[w];
    float m = lrelu(Ms + adv);
    float ex = __expf(lrelu(as_[w] + adv) - m);
    float den = ex;
    float2 v = *(const float2*)&xs[(size_t)w * 64 + 2 * lane];
    float2 acc = make_float2(v.x * ex, v.y * ex);

    int beg = g_ptr[w], end = g_ptr[w + 1];
    for (int e = beg; e < end; e++) {
        int s = g_csr[e];
        float exh = __expf(lrelu(as_[s] + adv) - m);
        den += exh;
        float2 u = *(const float2*)&xs[(size_t)s * 64 + 2 * lane];
        acc.x += u.x * exh;
        acc.y += u.y * exh;
    }
    float r = 1.0f / den;
    float2 b = *(const float2*)&bias[2 * lane];
    float2 o = make_float2(acc.x * r + b.x, acc.y * r + b.y);
    *(float2*)&out[(size_t)w * 64 + 2 * lane] = o;
}

// ---------------- launcher ----------------
extern "C" void kernel_launch(void* const* d_in, const int* in_sizes, int n_in,
                              void* d_out, int out_size) {
    const float* x    = (const float*)d_in[0];
    const void*  ei   = d_in[1];
    const float* W1   = (const float*)d_in[2];
    const float* at1s = (const float*)d_in[3];
    const float* at1d = (const float*)d_in[4];
    const float* b1   = (const float*)d_in[5];
    const float* W2   = (const float*)d_in[6];
    const float* at2s = (const float*)d_in[7];
    const float* at2d = (const float*)d_in[8];
    const float* b2   = (const float*)d_in[9];
    float* out = (float*)d_out;

    int Nn = in_sizes[0] / 128;   // 50000
    int E  = in_sizes[1] / 2;     // 800000

    float *xs1, *h, *xs2, *as1, *ad1, *as2, *ad2;
    cudaGetSymbolAddress((void**)&xs1, g_xs1);
    cudaGetSymbolAddress((void**)&h,   g_h);
    cudaGetSymbolAddress((void**)&xs2, g_xs2);
    cudaGetSymbolAddress((void**)&as1, g_as1);
    cudaGetSymbolAddress((void**)&ad1, g_ad1);
    cudaGetSymbolAddress((void**)&as2, g_as2);
    cudaGetSymbolAddress((void**)&ad2, g_ad2);

    const int T = 256;
    int nodeBlocks = (Nn + T - 1) / T;
    int edgeBlocks = (E + T - 1) / T;
    int warpNodeBlocks = (Nn * 32 + T - 1) / T;   // warp per node

    // init + edge dtype detection + CSR build
    k_init<<<nodeBlocks, T>>>(Nn);
    k_detect<<<edgeBlocks, T>>>((const int*)ei, E);
    k_hist<<<edgeBlocks, T>>>(ei, E);
    k_scan<<<1, 1024>>>(Nn);
    k_scatter<<<edgeBlocks, T>>>(ei, E);

    // ---- Layer 1 (H=8, C=32) ----
    {
        dim3 grid(256 / 64, (Nn + 127) / 128);
        k_gemm<<<grid, T>>>(x, W1, xs1, Nn, 256, 128);
    }
    k_scores1<<<warpNodeBlocks, T>>>(xs1, at1s, at1d, as1, ad1, Nn);
    k_agg1<<<warpNodeBlocks, T>>>(as1, ad1, xs1, b1, h, Nn);

    // ---- Layer 2 (H=1, C=64) ----
    {
        dim3 grid(64 / 64, (Nn + 127) / 128);
        k_gemm<<<grid, T>>>(h, W2, xs2, Nn, 64, 256);
    }
    k_scores2<<<warpNodeBlocks, T>>>(xs2, at2s, at2d, as2, ad2, Nn);
    k_agg2<<<warpNodeBlocks, T>>>(as2, ad2, xs2, b2, out, Nn);
}

// round 5
// speedup vs baseline: 1.6067x; 1.1045x over previous
#include <cuda_runtime.h>
#include <cuda_bf16.h>
#include <cstdint>

#define NN 50000
#define EE 800000
#define SCAN_BLK 1024
#define NSB ((NN + SCAN_BLK - 1) / SCAN_BLK)

// ---------------- scratch (device globals, no allocation) ----------------
__device__ float g_xs1[NN * 256];
__device__ float g_h[NN * 256];
__device__ float g_xs2[NN * 64];
__device__ float g_as1[NN * 8];
__device__ float g_ad1[NN * 8];
__device__ float g_as2[NN];
__device__ float g_ad2[NN];
__device__ int   g_cnt[NN];
__device__ int   g_ptr[NN + 1];
__device__ int   g_cur[NN];
__device__ int   g_csr[EE];
__device__ int   g_bsum[NSB];
__device__ int   g_boff[NSB];
__device__ float g_Ms1;
__device__ float g_Ms2;
__device__ int   g_is64;

// ---------------- helpers ----------------
__device__ __forceinline__ float lrelu(float a) { return a > 0.0f ? a : 0.2f * a; }

__device__ __forceinline__ void atomicMaxF(float* addr, float v) {
    if (v >= 0.0f) atomicMax((int*)addr, __float_as_int(v));
    else           atomicMin((unsigned int*)addr, __float_as_uint(v));
}

__device__ __forceinline__ void load_edge(const void* ei, int e, int E, int& s, int& d) {
    if (g_is64) {
        const long long* p = (const long long*)ei;
        s = (int)p[e];
        d = (int)p[E + e];
    } else {
        const int* p = (const int*)ei;
        s = p[e];
        d = p[E + e];
    }
}

__device__ __forceinline__ void ffma2(unsigned long long& d,
                                      unsigned long long a, unsigned long long b) {
    asm("fma.rn.f32x2 %0, %1, %2, %0;" : "+l"(d) : "l"(a), "l"(b));
}

// ---------------- init + dtype detect ----------------
__global__ void k_init(int n) {
    int i = blockIdx.x * blockDim.x + threadIdx.x;
    if (i < n) g_cnt[i] = 0;
    if (i == 0) { g_Ms1 = -1e30f; g_Ms2 = -1e30f; g_is64 = 1; }
}

__global__ void k_detect(const int* e32, int E) {
    int i = blockIdx.x * blockDim.x + threadIdx.x;
    if (i < E) { if (e32[2 * i + 1] != 0) g_is64 = 0; }
}

// ---------------- CSR build ----------------
__global__ void k_hist(const void* __restrict__ ei, int E) {
    int e = blockIdx.x * blockDim.x + threadIdx.x;
    if (e >= E) return;
    int s, d; load_edge(ei, e, E, s, d);
    atomicAdd(&g_cnt[d], 1);
}

// multi-block scan, stage 1: per-block exclusive scan + block totals
__global__ void k_scan1(int n) {
    __shared__ int ws[32];
    int i = blockIdx.x * SCAN_BLK + threadIdx.x;
    int lane = threadIdx.x & 31, wid = threadIdx.x >> 5;
    int v = (i < n) ? g_cnt[i] : 0;
    int x = v;
#pragma unroll
    for (int o = 1; o < 32; o <<= 1) {
        int t = __shfl_up_sync(0xffffffffu, x, o);
        if (lane >= o) x += t;
    }
    if (lane == 31) ws[wid] = x;
    __syncthreads();
    if (wid == 0) {
        int w = ws[lane];
#pragma unroll
        for (int o = 1; o < 32; o <<= 1) {
            int t = __shfl_up_sync(0xffffffffu, w, o);
            if (lane >= o) w += t;
        }
        ws[lane] = w;
    }
    __syncthreads();
    int excl = x - v + (wid ? ws[wid - 1] : 0);
    if (i < n) g_ptr[i] = excl;
    if (threadIdx.x == SCAN_BLK - 1) g_bsum[blockIdx.x] = excl + v;
}

// stage 2: inclusive scan of block sums (NSB <= 64)
__global__ void k_scan2(int nb) {
    __shared__ int ws2[2];
    int lane = threadIdx.x & 31, wid = threadIdx.x >> 5;
    int v = (threadIdx.x < nb) ? g_bsum[threadIdx.x] : 0;
    int x = v;
#pragma unroll
    for (int o = 1; o < 32; o <<= 1) {
        int t = __shfl_up_sync(0xffffffffu, x, o);
        if (lane >= o) x += t;
    }
    if (lane == 31) ws2[wid] = x;
    __syncthreads();
    if (wid == 1) x += ws2[0];
    if (threadIdx.x < nb) g_boff[threadIdx.x] = x;
}

// stage 3: add block offsets, init cursor, write total
__global__ void k_scan3(int n, int nb) {
    int i = blockIdx.x * blockDim.x + threadIdx.x;
    if (i < n) {
        int b = i / SCAN_BLK;
        int p = g_ptr[i] + (b ? g_boff[b - 1] : 0);
        g_ptr[i] = p;
        g_cur[i] = p;
    }
    if (i == 0) g_ptr[n] = g_boff[nb - 1];
}

__global__ void k_scatter(const void* __restrict__ ei, int E) {
    int e = blockIdx.x * blockDim.x + threadIdx.x;
    if (e >= E) return;
    int s, d; load_edge(ei, e, E, s, d);
    int pos = atomicAdd(&g_cur[d], 1);
    g_csr[pos] = s;
}

// ---------------- GEMM + fused attention scores ----------------
// C[M,N] = A[M,K] @ B[K,N] via fma.rn.f32x2, 128x64 tile, BK=16, 256 threads.
// Epilogue: per-row dot of C-tile columns with attS/attD (HC cols per head),
// producing as_/ad_ (HT = N/HC heads total), plus global max of a_src.
template<int HC, int HT>
__global__ void __launch_bounds__(256) k_gemm_sc(const float* __restrict__ A,
                                                 const float* __restrict__ B,
                                                 float* __restrict__ C,
                                                 const float* __restrict__ attS,
                                                 const float* __restrict__ attD,
                                                 float* __restrict__ AS,
                                                 float* __restrict__ AD,
                                                 float* gMs,
                                                 int M, int N, int K) {
    __shared__ __align__(16) float As[16][128];   // [k][m] transposed
    __shared__ __align__(16) float Bsd[16][128];  // [k][2n] duplicated pairs
    __shared__ float smx[8];
    int tid = threadIdx.x;
    int tx = tid & 15, ty = tid >> 4;
    int row0 = blockIdx.y * 128, col0 = blockIdx.x * 64;

    int am = tid >> 1;            // 0..127
    int ak = (tid & 1) * 8;       // 0 or 8
    int bk = tid >> 4;            // 0..15
    int bn = (tid & 15) * 4;      // 0..60

    unsigned long long acc[4][4];
#pragma unroll
    for (int i = 0; i < 4; i++)
#pragma unroll
        for (int j = 0; j < 4; j++) acc[i][j] = 0ull;

    for (int kb = 0; kb < K; kb += 16) {
        float4 a0 = make_float4(0.f, 0.f, 0.f, 0.f), a1 = a0;
        int gr = row0 + am;
        if (gr < M) {
            a0 = *(const float4*)&A[(size_t)gr * K + kb + ak];
            a1 = *(const float4*)&A[(size_t)gr * K + kb + ak + 4];
        }
        As[ak + 0][am] = a0.x; As[ak + 1][am] = a0.y;
        As[ak + 2][am] = a0.z; As[ak + 3][am] = a0.w;
        As[ak + 4][am] = a1.x; As[ak + 5][am] = a1.y;
        As[ak + 6][am] = a1.z; As[ak + 7][am] = a1.w;

        float4 b = *(const float4*)&B[(size_t)(kb + bk) * N + col0 + bn];
        *(float4*)&Bsd[bk][2 * bn]     = make_float4(b.x, b.x, b.y, b.y);
        *(float4*)&Bsd[bk][2 * bn + 4] = make_float4(b.z, b.z, b.w, b.w);
        __syncthreads();

#pragma unroll
        for (int k = 0; k < 16; k++) {
            ulonglong2 pa = *(const ulonglong2*)&As[k][ty * 8];
            ulonglong2 pb = *(const ulonglong2*)&As[k][ty * 8 + 4];
            ulonglong2 qa = *(const ulonglong2*)&Bsd[k][tx * 8];
            ulonglong2 qb = *(const ulonglong2*)&Bsd[k][tx * 8 + 4];
            unsigned long long p[4] = { pa.x, pa.y, pb.x, pb.y };
            unsigned long long q[4] = { qa.x, qa.y, qb.x, qb.y };
#pragma unroll
            for (int i = 0; i < 4; i++)
#pragma unroll
                for (int j = 0; j < 4; j++) ffma2(acc[i][j], p[i], q[j]);
        }
        __syncthreads();
    }

    // attention vector fragments for this thread's columns
    float4 sa = *(const float4*)&attS[col0 + tx * 4];
    float4 da = *(const float4*)&attD[col0 + tx * 4];
    const float* sap = (const float*)&sa;
    const float* dap = (const float*)&da;
    constexpr int GRP = HC / 4;           // lanes per head group (8 or 16)
    int head_base = col0 / HC;
    float mloc = -1e30f;

#pragma unroll
    for (int i = 0; i < 4; i++) {
        float2 c[4];
#pragma unroll
        for (int j = 0; j < 4; j++) c[j] = *(float2*)&acc[i][j];
        int r = row0 + ty * 8 + 2 * i;
        if (r < M)
            *(float4*)&C[(size_t)r * N + col0 + tx * 4] =
                make_float4(c[0].x, c[1].x, c[2].x, c[3].x);
        if (r + 1 < M)
            *(float4*)&C[(size_t)(r + 1) * N + col0 + tx * 4] =
                make_float4(c[0].y, c[1].y, c[2].y, c[3].y);

        // per-row partial dots with attention vectors
        float2 ps = make_float2(0.f, 0.f), pd = make_float2(0.f, 0.f);
#pragma unroll
        for (int j = 0; j < 4; j++) {
            ps.x += c[j].x * sap[j]; ps.y += c[j].y * sap[j];
            pd.x += c[j].x * dap[j]; pd.y += c[j].y * dap[j];
        }
#pragma unroll
        for (int o = 1; o < GRP; o <<= 1) {
            ps.x += __shfl_xor_sync(0xffffffffu, ps.x, o);
            ps.y += __shfl_xor_sync(0xffffffffu, ps.y, o);
            pd.x += __shfl_xor_sync(0xffffffffu, pd.x, o);
            pd.y += __shfl_xor_sync(0xffffffffu, pd.y, o);
        }
        if ((tx & (GRP - 1)) == 0) {
            int head = head_base + tx / GRP;
            if (r < M) {
                AS[(size_t)r * HT + head] = ps.x;
                AD[(size_t)r * HT + head] = pd.x;
                mloc = fmaxf(mloc, ps.x);
            }
            if (r + 1 < M) {
                AS[(size_t)(r + 1) * HT + head] = ps.y;
                AD[(size_t)(r + 1) * HT + head] = pd.y;
                mloc = fmaxf(mloc, ps.y);
            }
        }
    }
    // block max of a_src -> global
    int lane = tid & 31;
#pragma unroll
    for (int o = 16; o > 0; o >>= 1)
        mloc = fmaxf(mloc, __shfl_xor_sync(0xffffffffu, mloc, o));
    if (lane == 0) smx[tid >> 5] = mloc;
    __syncthreads();
    if (tid == 0) {
        float m = smx[0];
#pragma unroll
        for (int i = 1; i < 8; i++) m = fmaxf(m, smx[i]);
        atomicMaxF(gMs, m);
    }
}

// ---------------- fused aggregate layer 1 (warp per dest, H=8, C=32) ----------------
__global__ void k_agg1(const float* __restrict__ as_, const float* __restrict__ ad_,
                       const float* __restrict__ xs, const float* __restrict__ bias,
                       float* __restrict__ hout, int n) {
    int w = (blockIdx.x * blockDim.x + threadIdx.x) >> 5;
    int lane = threadIdx.x & 31;
    if (w >= n) return;
    float Ms = g_Ms1;

    float as_h = 0.f, ad_h = 0.f, m = 0.f;
    if (lane < 8) {
        as_h = as_[w * 8 + lane];
        ad_h = ad_[w * 8 + lane];
        m = lrelu(Ms + ad_h);
    }
    float ex = (lane < 8) ? __expf(lrelu(as_h + ad_h) - m) : 0.f;
    float den = ex;

    int hsel = lane >> 3;                    // 0..3
    float elo = __shfl_sync(0xffffffffu, ex, hsel);
    float ehi = __shfl_sync(0xffffffffu, ex, 4 + hsel);

    const float* xr = xs + (size_t)w * 256;
    float4 v0 = *(const float4*)&xr[4 * lane];
    float4 v1 = *(const float4*)&xr[128 + 4 * lane];
    float4 a0 = make_float4(v0.x * elo, v0.y * elo, v0.z * elo, v0.w * elo);
    float4 a1 = make_float4(v1.x * ehi, v1.y * ehi, v1.z * ehi, v1.w * ehi);

    int beg = g_ptr[w], end = g_ptr[w + 1];
    int s = (beg < end) ? g_csr[beg] : 0;
    for (int e = beg; e < end; e++) {
        int snext = (e + 1 < end) ? g_csr[e + 1] : 0;
        float exh = 0.f;
        if (lane < 8) {
            float a = lrelu(as_[s * 8 + lane] + ad_h);
            exh = __expf(a - m);
            den += exh;
        }
        float flo = __shfl_sync(0xffffffffu, exh, hsel);
        float fhi = __shfl_sync(0xffffffffu, exh, 4 + hsel);
        const float* ur = xs + (size_t)s * 256;
        float4 u0 = *(const float4*)&ur[4 * lane];
        float4 u1 = *(const float4*)&ur[128 + 4 * lane];
        a0.x += u0.x * flo; a0.y += u0.y * flo; a0.z += u0.z * flo; a0.w += u0.w * flo;
        a1.x += u1.x * fhi; a1.y += u1.y * fhi; a1.z += u1.z * fhi; a1.w += u1.w * fhi;
        s = snext;
    }

    float dlo = __shfl_sync(0xffffffffu, den, hsel);
    float dhi = __shfl_sync(0xffffffffu, den, 4 + hsel);
    float rlo = 1.0f / dlo, rhi = 1.0f / dhi;
    float4 blo = *(const float4*)&bias[4 * lane];
    float4 bhi = *(const float4*)&bias[128 + 4 * lane];
    float4 o0, o1;
    o0.x = a0.x * rlo + blo.x; o0.y = a0.y * rlo + blo.y;
    o0.z = a0.z * rlo + blo.z; o0.w = a0.w * rlo + blo.w;
    o1.x = a1.x * rhi + bhi.x; o1.y = a1.y * rhi + bhi.y;
    o1.z = a1.z * rhi + bhi.z; o1.w = a1.w * rhi + bhi.w;
    o0.x = o0.x > 0.f ? o0.x : (expf(o0.x) - 1.f);
    o0.y = o0.y > 0.f ? o0.y : (expf(o0.y) - 1.f);
    o0.z = o0.z > 0.f ? o0.z : (expf(o0.z) - 1.f);
    o0.w = o0.w > 0.f ? o0.w : (expf(o0.w) - 1.f);
    o1.x = o1.x > 0.f ? o1.x : (expf(o1.x) - 1.f);
    o1.y = o1.y > 0.f ? o1.y : (expf(o1.y) - 1.f);
    o1.z = o1.z > 0.f ? o1.z : (expf(o1.z) - 1.f);
    o1.w = o1.w > 0.f ? o1.w : (expf(o1.w) - 1.f);
    float* hr = hout + (size_t)w * 256;
    *(float4*)&hr[4 * lane] = o0;
    *(float4*)&hr[128 + 4 * lane] = o1;
}

// ---------------- fused aggregate layer 2 (warp per dest, H=1, C=64) ----------------
__global__ void k_agg2(const float* __restrict__ as_, const float* __restrict__ ad_,
                       const float* __restrict__ xs, const float* __restrict__ bias,
                       float* __restrict__ out, int n) {
    int w = (blockIdx.x * blockDim.x + threadIdx.x) >> 5;
    int lane = threadIdx.x & 31;
    if (w >= n) return;
    float Ms = g_Ms2;
    float adv = ad_[w];
    float m = lrelu(Ms + adv);
    float ex = __expf(lrelu(as_[w] + adv) - m);
    float den = ex;
    float2 v = *(const float2*)&xs[(size_t)w * 64 + 2 * lane];
    float2 acc = make_float2(v.x * ex, v.y * ex);

    int beg = g_ptr[w], end = g_ptr[w + 1];
    int s = (beg < end) ? g_csr[beg] : 0;
    for (int e = beg; e < end; e++) {
        int snext = (e + 1 < end) ? g_csr[e + 1] : 0;
        float exh = __expf(lrelu(as_[s] + adv) - m);
        den += exh;
        float2 u = *(const float2*)&xs[(size_t)s * 64 + 2 * lane];
        acc.x += u.x * exh;
        acc.y += u.y * exh;
        s = snext;
    }
    float r = 1.0f / den;
    float2 b = *(const float2*)&bias[2 * lane];
    *(float2*)&out[(size_t)w * 64 + 2 * lane] =
        make_float2(acc.x * r + b.x, acc.y * r + b.y);
}

// ---------------- launcher ----------------
extern "C" void kernel_launch(void* const* d_in, const int* in_sizes, int n_in,
                              void* d_out, int out_size) {
    const float* x    = (const float*)d_in[0];
    const void*  ei   = d_in[1];
    const float* W1   = (const float*)d_in[2];
    const float* at1s = (const float*)d_in[3];
    const float* at1d = (const float*)d_in[4];
    const float* b1   = (const float*)d_in[5];
    const float* W2   = (const float*)d_in[6];
    const float* at2s = (const float*)d_in[7];
    const float* at2d = (const float*)d_in[8];
    const float* b2   = (const float*)d_in[9];
    float* out = (float*)d_out;

    int Nn = in_sizes[0] / 128;   // 50000
    int E  = in_sizes[1] / 2;     // 800000

    float *xs1, *h, *xs2, *as1, *ad1, *as2, *ad2, *Ms1, *Ms2;
    cudaGetSymbolAddress((void**)&xs1, g_xs1);
    cudaGetSymbolAddress((void**)&h,   g_h);
    cudaGetSymbolAddress((void**)&xs2, g_xs2);
    cudaGetSymbolAddress((void**)&as1, g_as1);
    cudaGetSymbolAddress((void**)&ad1, g_ad1);
    cudaGetSymbolAddress((void**)&as2, g_as2);
    cudaGetSymbolAddress((void**)&ad2, g_ad2);
    cudaGetSymbolAddress((void**)&Ms1, g_Ms1);
    cudaGetSymbolAddress((void**)&Ms2, g_Ms2);

    const int T = 256;
    int nodeBlocks = (Nn + T - 1) / T;
    int edgeBlocks = (E + T - 1) / T;
    int warpNodeBlocks = (Nn * 32 + T - 1) / T;
    int nsb = (Nn + SCAN_BLK - 1) / SCAN_BLK;

    // init + dtype detection + CSR build (multi-block scan)
    k_init<<<nodeBlocks, T>>>(Nn);
    k_detect<<<edgeBlocks, T>>>((const int*)ei, E);
    k_hist<<<edgeBlocks, T>>>(ei, E);
    k_scan1<<<nsb, SCAN_BLK>>>(Nn);
    k_scan2<<<1, 64>>>(nsb);
    k_scan3<<<nodeBlocks, T>>>(Nn, nsb);
    k_scatter<<<edgeBlocks, T>>>(ei, E);

    // ---- Layer 1 (H=8, C=32) ----
    {
        dim3 grid(256 / 64, (Nn + 127) / 128);
        k_gemm_sc<32, 8><<<grid, T>>>(x, W1, xs1, at1s, at1d, as1, ad1, Ms1,
                                      Nn, 256, 128);
    }
    k_agg1<<<warpNodeBlocks, T>>>(as1, ad1, xs1, b1, h, Nn);

    // ---- Layer 2 (H=1, C=64) ----
    {
        dim3 grid(1, (Nn + 127) / 128);
        k_gemm_sc<64, 1><<<grid, T>>>(h, W2, xs2, at2s, at2d, as2, ad2, Ms2,
                                      Nn, 64, 256);
    }
    k_agg2<<<warpNodeBlocks, T>>>(as2, ad2, xs2, b2, out, Nn);
}

// round 7
// speedup vs baseline: 1.7047x; 1.0610x over previous
#include <cuda_runtime.h>
#include <cuda_bf16.h>
#include <cstdint>

#define NN 50000
#define EE 800000
#define SCAN_BLK 1024
#define NSB ((NN + SCAN_BLK - 1) / SCAN_BLK)

// ---------------- scratch (device globals, no allocation) ----------------
__device__ float g_xs1[NN * 256];
__device__ float g_h[NN * 256];
__device__ float g_xs2[NN * 64];
__device__ float g_as1[NN * 8];
__device__ float g_ad1[NN * 8];
__device__ float g_as2[NN];
__device__ float g_ad2[NN];
__device__ int   g_cnt[NN];
__device__ int   g_ptr[NN + 1];
__device__ int   g_cur[NN];
__device__ int   g_csr[EE];
__device__ int   g_bsum[NSB];
__device__ int   g_boff[NSB];
__device__ float g_Ms1;
__device__ float g_Ms2;
__device__ int   g_is64;

// ---------------- helpers ----------------
__device__ __forceinline__ float lrelu(float a) { return a > 0.0f ? a : 0.2f * a; }

__device__ __forceinline__ void atomicMaxF(float* addr, float v) {
    if (v >= 0.0f) atomicMax((int*)addr, __float_as_int(v));
    else           atomicMin((unsigned int*)addr, __float_as_uint(v));
}

__device__ __forceinline__ void load_edge(const void* ei, int e, int E, int& s, int& d) {
    if (g_is64) {
        const long long* p = (const long long*)ei;
        s = (int)p[e];
        d = (int)p[E + e];
    } else {
        const int* p = (const int*)ei;
        s = p[e];
        d = p[E + e];
    }
}

__device__ __forceinline__ void ffma2(unsigned long long& d,
                                      unsigned long long a, unsigned long long b) {
    asm("fma.rn.f32x2 %0, %1, %2, %0;" : "+l"(d) : "l"(a), "l"(b));
}

// ---------------- init + dtype detect ----------------
__global__ void k_init(int n) {
    int i = blockIdx.x * blockDim.x + threadIdx.x;
    if (i < n) g_cnt[i] = 0;
    if (i == 0) g_is64 = 1;
}

__global__ void k_init_ms() { g_Ms1 = -1e30f; g_Ms2 = -1e30f; }

__global__ void k_detect(const int* e32, int E) {
    int i = blockIdx.x * blockDim.x + threadIdx.x;
    if (i < E) { if (e32[2 * i + 1] != 0) g_is64 = 0; }
}

// ---------------- CSR build ----------------
__global__ void k_hist(const void* __restrict__ ei, int E) {
    int e = blockIdx.x * blockDim.x + threadIdx.x;
    if (e >= E) return;
    int s, d; load_edge(ei, e, E, s, d);
    atomicAdd(&g_cnt[d], 1);
}

__global__ void k_scan1(int n) {
    __shared__ int ws[32];
    int i = blockIdx.x * SCAN_BLK + threadIdx.x;
    int lane = threadIdx.x & 31, wid = threadIdx.x >> 5;
    int v = (i < n) ? g_cnt[i] : 0;
    int x = v;
#pragma unroll
    for (int o = 1; o < 32; o <<= 1) {
        int t = __shfl_up_sync(0xffffffffu, x, o);
        if (lane >= o) x += t;
    }
    if (lane == 31) ws[wid] = x;
    __syncthreads();
    if (wid == 0) {
        int w = ws[lane];
#pragma unroll
        for (int o = 1; o < 32; o <<= 1) {
            int t = __shfl_up_sync(0xffffffffu, w, o);
            if (lane >= o) w += t;
        }
        ws[lane] = w;
    }
    __syncthreads();
    int excl = x - v + (wid ? ws[wid - 1] : 0);
    if (i < n) g_ptr[i] = excl;
    if (threadIdx.x == SCAN_BLK - 1) g_bsum[blockIdx.x] = excl + v;
}

__global__ void k_scan2(int nb) {
    __shared__ int ws2[2];
    int lane = threadIdx.x & 31, wid = threadIdx.x >> 5;
    int v = (threadIdx.x < nb) ? g_bsum[threadIdx.x] : 0;
    int x = v;
#pragma unroll
    for (int o = 1; o < 32; o <<= 1) {
        int t = __shfl_up_sync(0xffffffffu, x, o);
        if (lane >= o) x += t;
    }
    if (lane == 31) ws2[wid] = x;
    __syncthreads();
    if (wid == 1) x += ws2[0];
    if (threadIdx.x < nb) g_boff[threadIdx.x] = x;
}

__global__ void k_scan3(int n, int nb) {
    int i = blockIdx.x * blockDim.x + threadIdx.x;
    if (i < n) {
        int b = i / SCAN_BLK;
        int p = g_ptr[i] + (b ? g_boff[b - 1] : 0);
        g_ptr[i] = p;
        g_cur[i] = p;
    }
    if (i == 0) g_ptr[n] = g_boff[nb - 1];
}

__global__ void k_scatter(const void* __restrict__ ei, int E) {
    int e = blockIdx.x * blockDim.x + threadIdx.x;
    if (e >= E) return;
    int s, d; load_edge(ei, e, E, s, d);
    int pos = atomicAdd(&g_cur[d], 1);
    g_csr[pos] = s;
}

// ---------------- GEMM + fused attention scores ----------------
template<int HC, int HT>
__global__ void __launch_bounds__(256) k_gemm_sc(const float* __restrict__ A,
                                                 const float* __restrict__ B,
                                                 float* __restrict__ C,
                                                 const float* __restrict__ attS,
                                                 const float* __restrict__ attD,
                                                 float* __restrict__ AS,
                                                 float* __restrict__ AD,
                                                 float* gMs,
                                                 int M, int N, int K) {
    __shared__ __align__(16) float As[16][128];   // [k][m] transposed
    __shared__ __align__(16) float Bsd[16][128];  // [k][2n] duplicated pairs
    __shared__ float smx[8];
    int tid = threadIdx.x;
    int tx = tid & 15, ty = tid >> 4;
    int row0 = blockIdx.y * 128, col0 = blockIdx.x * 64;

    int am = tid >> 1;
    int ak = (tid & 1) * 8;
    int bk = tid >> 4;
    int bn = (tid & 15) * 4;

    unsigned long long acc[4][4];
#pragma unroll
    for (int i = 0; i < 4; i++)
#pragma unroll
        for (int j = 0; j < 4; j++) acc[i][j] = 0ull;

    for (int kb = 0; kb < K; kb += 16) {
        float4 a0 = make_float4(0.f, 0.f, 0.f, 0.f), a1 = a0;
        int gr = row0 + am;
        if (gr < M) {
            a0 = *(const float4*)&A[(size_t)gr * K + kb + ak];
            a1 = *(const float4*)&A[(size_t)gr * K + kb + ak + 4];
        }
        As[ak + 0][am] = a0.x; As[ak + 1][am] = a0.y;
        As[ak + 2][am] = a0.z; As[ak + 3][am] = a0.w;
        As[ak + 4][am] = a1.x; As[ak + 5][am] = a1.y;
        As[ak + 6][am] = a1.z; As[ak + 7][am] = a1.w;

        float4 b = *(const float4*)&B[(size_t)(kb + bk) * N + col0 + bn];
        *(float4*)&Bsd[bk][2 * bn]     = make_float4(b.x, b.x, b.y, b.y);
        *(float4*)&Bsd[bk][2 * bn + 4] = make_float4(b.z, b.z, b.w, b.w);
        __syncthreads();

#pragma unroll
        for (int k = 0; k < 16; k++) {
            ulonglong2 pa = *(const ulonglong2*)&As[k][ty * 8];
            ulonglong2 pb = *(const ulonglong2*)&As[k][ty * 8 + 4];
            ulonglong2 qa = *(const ulonglong2*)&Bsd[k][tx * 8];
            ulonglong2 qb = *(const ulonglong2*)&Bsd[k][tx * 8 + 4];
            unsigned long long p[4] = { pa.x, pa.y, pb.x, pb.y };
            unsigned long long q[4] = { qa.x, qa.y, qb.x, qb.y };
#pragma unroll
            for (int i = 0; i < 4; i++)
#pragma unroll
                for (int j = 0; j < 4; j++) ffma2(acc[i][j], p[i], q[j]);
        }
        __syncthreads();
    }

    float4 sa = *(const float4*)&attS[col0 + tx * 4];
    float4 da = *(const float4*)&attD[col0 + tx * 4];
    const float* sap = (const float*)&sa;
    const float* dap = (const float*)&da;
    constexpr int GRP = HC / 4;
    int head_base = col0 / HC;
    float mloc = -1e30f;

#pragma unroll
    for (int i = 0; i < 4; i++) {
        float2 c[4];
#pragma unroll
        for (int j = 0; j < 4; j++) c[j] = *(float2*)&acc[i][j];
        int r = row0 + ty * 8 + 2 * i;
        if (r < M)
            *(float4*)&C[(size_t)r * N + col0 + tx * 4] =
                make_float4(c[0].x, c[1].x, c[2].x, c[3].x);
        if (r + 1 < M)
            *(float4*)&C[(size_t)(r + 1) * N + col0 + tx * 4] =
                make_float4(c[0].y, c[1].y, c[2].y, c[3].y);

        float2 ps = make_float2(0.f, 0.f), pd = make_float2(0.f, 0.f);
#pragma unroll
        for (int j = 0; j < 4; j++) {
            ps.x += c[j].x * sap[j]; ps.y += c[j].y * sap[j];
            pd.x += c[j].x * dap[j]; pd.y += c[j].y * dap[j];
        }
#pragma unroll
        for (int o = 1; o < GRP; o <<= 1) {
            ps.x += __shfl_xor_sync(0xffffffffu, ps.x, o);
            ps.y += __shfl_xor_sync(0xffffffffu, ps.y, o);
            pd.x += __shfl_xor_sync(0xffffffffu, pd.x, o);
            pd.y += __shfl_xor_sync(0xffffffffu, pd.y, o);
        }
        if ((tx & (GRP - 1)) == 0) {
            int head = head_base + tx / GRP;
            if (r < M) {
                AS[(size_t)r * HT + head] = ps.x;
                AD[(size_t)r * HT + head] = pd.x;
                mloc = fmaxf(mloc, ps.x);
            }
            if (r + 1 < M) {
                AS[(size_t)(r + 1) * HT + head] = ps.y;
                AD[(size_t)(r + 1) * HT + head] = pd.y;
                mloc = fmaxf(mloc, ps.y);
            }
        }
    }
    int lane = tid & 31;
#pragma unroll
    for (int o = 16; o > 0; o >>= 1)
        mloc = fmaxf(mloc, __shfl_xor_sync(0xffffffffu, mloc, o));
    if (lane == 0) smx[tid >> 5] = mloc;
    __syncthreads();
    if (tid == 0) {
        float m = smx[0];
#pragma unroll
        for (int i = 1; i < 8; i++) m = fmaxf(m, smx[i]);
        atomicMaxF(gMs, m);
    }
}

// ---------------- fused aggregate layer 1 (warp per dest, H=8, C=32) ----------------
__global__ void k_agg1(const float* __restrict__ as_, const float* __restrict__ ad_,
                       const float* __restrict__ xs, const float* __restrict__ bias,
                       float* __restrict__ hout, int n) {
    int w = (blockIdx.x * blockDim.x + threadIdx.x) >> 5;
    int lane = threadIdx.x & 31;
    if (w >= n) return;
    float Ms = g_Ms1;

    float as_h = 0.f, ad_h = 0.f, m = 0.f;
    if (lane < 8) {
        as_h = as_[w * 8 + lane];
        ad_h = ad_[w * 8 + lane];
        m = lrelu(Ms + ad_h);
    }
    float ex = (lane < 8) ? __expf(lrelu(as_h + ad_h) - m) : 0.f;
    float den = ex;

    int hsel = lane >> 3;
    float elo = __shfl_sync(0xffffffffu, ex, hsel);
    float ehi = __shfl_sync(0xffffffffu, ex, 4 + hsel);

    const float* xr = xs + (size_t)w * 256;
    float4 v0 = *(const float4*)&xr[4 * lane];
    float4 v1 = *(const float4*)&xr[128 + 4 * lane];
    float4 a0 = make_float4(v0.x * elo, v0.y * elo, v0.z * elo, v0.w * elo);
    float4 a1 = make_float4(v1.x * ehi, v1.y * ehi, v1.z * ehi, v1.w * ehi);

    int beg = g_ptr[w], end = g_ptr[w + 1];
    int e = beg;
    // 2x unrolled: two independent edge chains per iteration for MLP
    for (; e + 2 <= end; e += 2) {
        int sA = g_csr[e];
        int sB = g_csr[e + 1];
        float exA = 0.f, exB = 0.f;
        if (lane < 8) {
            float aA = lrelu(as_[sA * 8 + lane] + ad_h);
            float aB = lrelu(as_[sB * 8 + lane] + ad_h);
            exA = __expf(aA - m);
            exB = __expf(aB - m);
            den += exA + exB;
        }
        const float* urA = xs + (size_t)sA * 256;
        const float* urB = xs + (size_t)sB * 256;
        float4 uA0 = *(const float4*)&urA[4 * lane];
        float4 uA1 = *(const float4*)&urA[128 + 4 * lane];
        float4 uB0 = *(const float4*)&urB[4 * lane];
        float4 uB1 = *(const float4*)&urB[128 + 4 * lane];
        float fAlo = __shfl_sync(0xffffffffu, exA, hsel);
        float fAhi = __shfl_sync(0xffffffffu, exA, 4 + hsel);
        float fBlo = __shfl_sync(0xffffffffu, exB, hsel);
        float fBhi = __shfl_sync(0xffffffffu, exB, 4 + hsel);
        a0.x += uA0.x * fAlo; a0.y += uA0.y * fAlo; a0.z += uA0.z * fAlo; a0.w += uA0.w * fAlo;
        a1.x += uA1.x * fAhi; a1.y += uA1.y * fAhi; a1.z += uA1.z * fAhi; a1.w += uA1.w * fAhi;
        a0.x += uB0.x * fBlo; a0.y += uB0.y * fBlo; a0.z += uB0.z * fBlo; a0.w += uB0.w * fBlo;
        a1.x += uB1.x * fBhi; a1.y += uB1.y * fBhi; a1.z += uB1.z * fBhi; a1.w += uB1.w * fBhi;
    }
    if (e < end) {
        int s = g_csr[e];
        float exh = 0.f;
        if (lane < 8) {
            float a = lrelu(as_[s * 8 + lane] + ad_h);
            exh = __expf(a - m);
            den += exh;
        }
        float flo = __shfl_sync(0xffffffffu, exh, hsel);
        float fhi = __shfl_sync(0xffffffffu, exh, 4 + hsel);
        const float* ur = xs + (size_t)s * 256;
        float4 u0 = *(const float4*)&ur[4 * lane];
        float4 u1 = *(const float4*)&ur[128 + 4 * lane];
        a0.x += u0.x * flo; a0.y += u0.y * flo; a0.z += u0.z * flo; a0.w += u0.w * flo;
        a1.x += u1.x * fhi; a1.y += u1.y * fhi; a1.z += u1.z * fhi; a1.w += u1.w * fhi;
    }

    float dlo = __shfl_sync(0xffffffffu, den, hsel);
    float dhi = __shfl_sync(0xffffffffu, den, 4 + hsel);
    float rlo = 1.0f / dlo, rhi = 1.0f / dhi;
    float4 blo = *(const float4*)&bias[4 * lane];
    float4 bhi = *(const float4*)&bias[128 + 4 * lane];
    float4 o0, o1;
    o0.x = a0.x * rlo + blo.x; o0.y = a0.y * rlo + blo.y;
    o0.z = a0.z * rlo + blo.z; o0.w = a0.w * rlo + blo.w;
    o1.x = a1.x * rhi + bhi.x; o1.y = a1.y * rhi + bhi.y;
    o1.z = a1.z * rhi + bhi.z; o1.w = a1.w * rhi + bhi.w;
    o0.x = o0.x > 0.f ? o0.x : (expf(o0.x) - 1.f);
    o0.y = o0.y > 0.f ? o0.y : (expf(o0.y) - 1.f);
    o0.z = o0.z > 0.f ? o0.z : (expf(o0.z) - 1.f);
    o0.w = o0.w > 0.f ? o0.w : (expf(o0.w) - 1.f);
    o1.x = o1.x > 0.f ? o1.x : (expf(o1.x) - 1.f);
    o1.y = o1.y > 0.f ? o1.y : (expf(o1.y) - 1.f);
    o1.z = o1.z > 0.f ? o1.z : (expf(o1.z) - 1.f);
    o1.w = o1.w > 0.f ? o1.w : (expf(o1.w) - 1.f);
    float* hr = hout + (size_t)w * 256;
    *(float4*)&hr[4 * lane] = o0;
    *(float4*)&hr[128 + 4 * lane] = o1;
}

// ---------------- fused aggregate layer 2 (warp per dest, H=1, C=64) ----------------
__global__ void k_agg2(const float* __restrict__ as_, const float* __restrict__ ad_,
                       const float* __restrict__ xs, const float* __restrict__ bias,
                       float* __restrict__ out, int n) {
    int w = (blockIdx.x * blockDim.x + threadIdx.x) >> 5;
    int lane = threadIdx.x & 31;
    if (w >= n) return;
    float Ms = g_Ms2;
    float adv = ad_[w];
    float m = lrelu(Ms + adv);
    float ex = __expf(lrelu(as_[w] + adv) - m);
    float den = ex;
    float2 v = *(const float2*)&xs[(size_t)w * 64 + 2 * lane];
    float2 acc = make_float2(v.x * ex, v.y * ex);

    int beg = g_ptr[w], end = g_ptr[w + 1];
    int e = beg;
    for (; e + 2 <= end; e += 2) {
        int sA = g_csr[e];
        int sB = g_csr[e + 1];
        float aA = as_[sA];
        float aB = as_[sB];
        float2 uA = *(const float2*)&xs[(size_t)sA * 64 + 2 * lane];
        float2 uB = *(const float2*)&xs[(size_t)sB * 64 + 2 * lane];
        float exA = __expf(lrelu(aA + adv) - m);
        float exB = __expf(lrelu(aB + adv) - m);
        den += exA + exB;
        acc.x += uA.x * exA; acc.y += uA.y * exA;
        acc.x += uB.x * exB; acc.y += uB.y * exB;
    }
    if (e < end) {
        int s = g_csr[e];
        float exh = __expf(lrelu(as_[s] + adv) - m);
        den += exh;
        float2 u = *(const float2*)&xs[(size_t)s * 64 + 2 * lane];
        acc.x += u.x * exh;
        acc.y += u.y * exh;
    }
    float r = 1.0f / den;
    float2 b = *(const float2*)&bias[2 * lane];
    *(float2*)&out[(size_t)w * 64 + 2 * lane] =
        make_float2(acc.x * r + b.x, acc.y * r + b.y);
}

// ---------------- launcher ----------------
extern "C" void kernel_launch(void* const* d_in, const int* in_sizes, int n_in,
                              void* d_out, int out_size) {
    const float* x    = (const float*)d_in[0];
    const void*  ei   = d_in[1];
    const float* W1   = (const float*)d_in[2];
    const float* at1s = (const float*)d_in[3];
    const float* at1d = (const float*)d_in[4];
    const float* b1   = (const float*)d_in[5];
    const float* W2   = (const float*)d_in[6];
    const float* at2s = (const float*)d_in[7];
    const float* at2d = (const float*)d_in[8];
    const float* b2   = (const float*)d_in[9];
    float* out = (float*)d_out;

    int Nn = in_sizes[0] / 128;   // 50000
    int E  = in_sizes[1] / 2;     // 800000

    float *xs1, *h, *xs2, *as1, *ad1, *as2, *ad2, *Ms1, *Ms2;
    cudaGetSymbolAddress((void**)&xs1, g_xs1);
    cudaGetSymbolAddress((void**)&h,   g_h);
    cudaGetSymbolAddress((void**)&xs2, g_xs2);
    cudaGetSymbolAddress((void**)&as1, g_as1);
    cudaGetSymbolAddress((void**)&ad1, g_ad1);
    cudaGetSymbolAddress((void**)&as2, g_as2);
    cudaGetSymbolAddress((void**)&ad2, g_ad2);
    cudaGetSymbolAddress((void**)&Ms1, g_Ms1);
    cudaGetSymbolAddress((void**)&Ms2, g_Ms2);

    // one-time host-side resources (no device memory)
    static cudaStream_t s1 = nullptr;
    static cudaEvent_t evFork = nullptr, evJoin = nullptr;
    if (s1 == nullptr) {
        cudaStreamCreateWithFlags(&s1, cudaStreamNonBlocking);
        cudaEventCreateWithFlags(&evFork, cudaEventDisableTiming);
        cudaEventCreateWithFlags(&evJoin, cudaEventDisableTiming);
    }

    const int T = 256;
    int nodeBlocks = (Nn + T - 1) / T;
    int edgeBlocks = (E + T - 1) / T;
    int warpNodeBlocks = (Nn * 32 + T - 1) / T;
    int nsb = (Nn + SCAN_BLK - 1) / SCAN_BLK;

    // ---- fork: CSR build on side stream, GEMM1 on main stream ----
    cudaEventRecord(evFork, 0);
    cudaStreamWaitEvent(s1, evFork, 0);

    k_init<<<nodeBlocks, T, 0, s1>>>(Nn);
    k_detect<<<edgeBlocks, T, 0, s1>>>((const int*)ei, E);
    k_hist<<<edgeBlocks, T, 0, s1>>>(ei, E);
    k_scan1<<<nsb, SCAN_BLK, 0, s1>>>(Nn);
    k_scan2<<<1, 64, 0, s1>>>(nsb);
    k_scan3<<<nodeBlocks, T, 0, s1>>>(Nn, nsb);
    k_scatter<<<edgeBlocks, T, 0, s1>>>(ei, E);
    cudaEventRecord(evJoin, s1);

    // main stream: Ms init + GEMM1 with fused scores
    k_init_ms<<<1, 1>>>();
    {
        dim3 grid(256 / 64, (Nn + 127) / 128);
        k_gemm_sc<32, 8><<<grid, T>>>(x, W1, xs1, at1s, at1d, as1, ad1, Ms1,
                                      Nn, 256, 128);
    }

    // ---- join, then the serial tail ----
    cudaStreamWaitEvent(0, evJoin, 0);
    k_agg1<<<warpNodeBlocks, T>>>(as1, ad1, xs1, b1, h, Nn);

    {
        dim3 grid(1, (Nn + 127) / 128);
        k_gemm_sc<64, 1><<<grid, T>>>(h, W2, xs2, at2s, at2d, as2, ad2, Ms2,
                                      Nn, 64, 256);
    }
    k_agg2<<<warpNodeBlocks, T>>>(as2, ad2, xs2, b2, out, Nn);
}

// round 8
// speedup vs baseline: 1.7163x; 1.0068x over previous
#include <cuda_runtime.h>
#include <cuda_bf16.h>
#include <cstdint>

#define NN 50000
#define EE 800000
#define SCAN_BLK 1024
#define NSB ((NN + SCAN_BLK - 1) / SCAN_BLK)

// ---------------- scratch (device globals, no allocation) ----------------
__device__ float g_xs1[NN * 256];
__device__ float g_h[NN * 256];
__device__ float g_xs2[NN * 64];
__device__ float g_as1[NN * 8];
__device__ float g_ad1[NN * 8];
__device__ float g_as2[NN];
__device__ float g_ad2[NN];
__device__ int   g_cnt[NN];
__device__ int   g_ptr[NN + 1];
__device__ int   g_cur[NN];
__device__ int   g_csr[EE];
__device__ int   g_bsum[NSB];
__device__ int   g_boff[NSB];
__device__ float g_Ms1;
__device__ float g_Ms2;
__device__ int   g_is64;

// ---------------- helpers ----------------
__device__ __forceinline__ float lrelu(float a) { return a > 0.0f ? a : 0.2f * a; }

__device__ __forceinline__ void atomicMaxF(float* addr, float v) {
    if (v >= 0.0f) atomicMax((int*)addr, __float_as_int(v));
    else           atomicMin((unsigned int*)addr, __float_as_uint(v));
}

__device__ __forceinline__ void load_edge(const void* ei, int e, int E, int& s, int& d) {
    if (g_is64) {
        const long long* p = (const long long*)ei;
        s = (int)p[e];
        d = (int)p[E + e];
    } else {
        const int* p = (const int*)ei;
        s = p[e];
        d = p[E + e];
    }
}

__device__ __forceinline__ void ffma2(unsigned long long& d,
                                      unsigned long long a, unsigned long long b) {
    asm("fma.rn.f32x2 %0, %1, %2, %0;" : "+l"(d) : "l"(a), "l"(b));
}

// ---------------- init + dtype detect ----------------
__global__ void k_init(int n) {
    int i = blockIdx.x * blockDim.x + threadIdx.x;
    if (i < n) g_cnt[i] = 0;
    if (i == 0) g_is64 = 1;
}

__global__ void k_init_ms() { g_Ms1 = -1e30f; g_Ms2 = -1e30f; }

__global__ void k_detect(const int* e32, int E) {
    int i = blockIdx.x * blockDim.x + threadIdx.x;
    if (i < E) { if (e32[2 * i + 1] != 0) g_is64 = 0; }
}

// ---------------- CSR build ----------------
__global__ void k_hist(const void* __restrict__ ei, int E) {
    int e = blockIdx.x * blockDim.x + threadIdx.x;
    if (e >= E) return;
    int s, d; load_edge(ei, e, E, s, d);
    atomicAdd(&g_cnt[d], 1);
}

__global__ void k_scan1(int n) {
    __shared__ int ws[32];
    int i = blockIdx.x * SCAN_BLK + threadIdx.x;
    int lane = threadIdx.x & 31, wid = threadIdx.x >> 5;
    int v = (i < n) ? g_cnt[i] : 0;
    int x = v;
#pragma unroll
    for (int o = 1; o < 32; o <<= 1) {
        int t = __shfl_up_sync(0xffffffffu, x, o);
        if (lane >= o) x += t;
    }
    if (lane == 31) ws[wid] = x;
    __syncthreads();
    if (wid == 0) {
        int w = ws[lane];
#pragma unroll
        for (int o = 1; o < 32; o <<= 1) {
            int t = __shfl_up_sync(0xffffffffu, w, o);
            if (lane >= o) w += t;
        }
        ws[lane] = w;
    }
    __syncthreads();
    int excl = x - v + (wid ? ws[wid - 1] : 0);
    if (i < n) g_ptr[i] = excl;
    if (threadIdx.x == SCAN_BLK - 1) g_bsum[blockIdx.x] = excl + v;
}

__global__ void k_scan2(int nb) {
    __shared__ int ws2[2];
    int lane = threadIdx.x & 31, wid = threadIdx.x >> 5;
    int v = (threadIdx.x < nb) ? g_bsum[threadIdx.x] : 0;
    int x = v;
#pragma unroll
    for (int o = 1; o < 32; o <<= 1) {
        int t = __shfl_up_sync(0xffffffffu, x, o);
        if (lane >= o) x += t;
    }
    if (lane == 31) ws2[wid] = x;
    __syncthreads();
    if (wid == 1) x += ws2[0];
    if (threadIdx.x < nb) g_boff[threadIdx.x] = x;
}

__global__ void k_scan3(int n, int nb) {
    int i = blockIdx.x * blockDim.x + threadIdx.x;
    if (i < n) {
        int b = i / SCAN_BLK;
        int p = g_ptr[i] + (b ? g_boff[b - 1] : 0);
        g_ptr[i] = p;
        g_cur[i] = p;
    }
    if (i == 0) g_ptr[n] = g_boff[nb - 1];
}

__global__ void k_scatter(const void* __restrict__ ei, int E) {
    int e = blockIdx.x * blockDim.x + threadIdx.x;
    if (e >= E) return;
    int s, d; load_edge(ei, e, E, s, d);
    int pos = atomicAdd(&g_cur[d], 1);
    g_csr[pos] = s;
}

// ---------------- GEMM + fused attention scores ----------------
template<int HC, int HT>
__global__ void __launch_bounds__(256) k_gemm_sc(const float* __restrict__ A,
                                                 const float* __restrict__ B,
                                                 float* __restrict__ C,
                                                 const float* __restrict__ attS,
                                                 const float* __restrict__ attD,
                                                 float* __restrict__ AS,
                                                 float* __restrict__ AD,
                                                 float* gMs,
                                                 int M, int N, int K) {
    __shared__ __align__(16) float As[16][128];   // [k][m] transposed
    __shared__ __align__(16) float Bsd[16][128];  // [k][2n] duplicated pairs
    __shared__ float smx[8];
    int tid = threadIdx.x;
    int tx = tid & 15, ty = tid >> 4;
    int row0 = blockIdx.y * 128, col0 = blockIdx.x * 64;

    int am = tid >> 1;
    int ak = (tid & 1) * 8;
    int bk = tid >> 4;
    int bn = (tid & 15) * 4;

    unsigned long long acc[4][4];
#pragma unroll
    for (int i = 0; i < 4; i++)
#pragma unroll
        for (int j = 0; j < 4; j++) acc[i][j] = 0ull;

    for (int kb = 0; kb < K; kb += 16) {
        float4 a0 = make_float4(0.f, 0.f, 0.f, 0.f), a1 = a0;
        int gr = row0 + am;
        if (gr < M) {
            a0 = *(const float4*)&A[(size_t)gr * K + kb + ak];
            a1 = *(const float4*)&A[(size_t)gr * K + kb + ak + 4];
        }
        As[ak + 0][am] = a0.x; As[ak + 1][am] = a0.y;
        As[ak + 2][am] = a0.z; As[ak + 3][am] = a0.w;
        As[ak + 4][am] = a1.x; As[ak + 5][am] = a1.y;
        As[ak + 6][am] = a1.z; As[ak + 7][am] = a1.w;

        float4 b = *(const float4*)&B[(size_t)(kb + bk) * N + col0 + bn];
        *(float4*)&Bsd[bk][2 * bn]     = make_float4(b.x, b.x, b.y, b.y);
        *(float4*)&Bsd[bk][2 * bn + 4] = make_float4(b.z, b.z, b.w, b.w);
        __syncthreads();

#pragma unroll
        for (int k = 0; k < 16; k++) {
            ulonglong2 pa = *(const ulonglong2*)&As[k][ty * 8];
            ulonglong2 pb = *(const ulonglong2*)&As[k][ty * 8 + 4];
            ulonglong2 qa = *(const ulonglong2*)&Bsd[k][tx * 8];
            ulonglong2 qb = *(const ulonglong2*)&Bsd[k][tx * 8 + 4];
            unsigned long long p[4] = { pa.x, pa.y, pb.x, pb.y };
            unsigned long long q[4] = { qa.x, qa.y, qb.x, qb.y };
#pragma unroll
            for (int i = 0; i < 4; i++)
#pragma unroll
                for (int j = 0; j < 4; j++) ffma2(acc[i][j], p[i], q[j]);
        }
        __syncthreads();
    }

    float4 sa = *(const float4*)&attS[col0 + tx * 4];
    float4 da = *(const float4*)&attD[col0 + tx * 4];
    const float* sap = (const float*)&sa;
    const float* dap = (const float*)&da;
    constexpr int GRP = HC / 4;
    int head_base = col0 / HC;
    float mloc = -1e30f;

#pragma unroll
    for (int i = 0; i < 4; i++) {
        float2 c[4];
#pragma unroll
        for (int j = 0; j < 4; j++) c[j] = *(float2*)&acc[i][j];
        int r = row0 + ty * 8 + 2 * i;
        if (r < M)
            *(float4*)&C[(size_t)r * N + col0 + tx * 4] =
                make_float4(c[0].x, c[1].x, c[2].x, c[3].x);
        if (r + 1 < M)
            *(float4*)&C[(size_t)(r + 1) * N + col0 + tx * 4] =
                make_float4(c[0].y, c[1].y, c[2].y, c[3].y);

        float2 ps = make_float2(0.f, 0.f), pd = make_float2(0.f, 0.f);
#pragma unroll
        for (int j = 0; j < 4; j++) {
            ps.x += c[j].x * sap[j]; ps.y += c[j].y * sap[j];
            pd.x += c[j].x * dap[j]; pd.y += c[j].y * dap[j];
        }
#pragma unroll
        for (int o = 1; o < GRP; o <<= 1) {
            ps.x += __shfl_xor_sync(0xffffffffu, ps.x, o);
            ps.y += __shfl_xor_sync(0xffffffffu, ps.y, o);
            pd.x += __shfl_xor_sync(0xffffffffu, pd.x, o);
            pd.y += __shfl_xor_sync(0xffffffffu, pd.y, o);
        }
        if ((tx & (GRP - 1)) == 0) {
            int head = head_base + tx / GRP;
            if (r < M) {
                AS[(size_t)r * HT + head] = ps.x;
                AD[(size_t)r * HT + head] = pd.x;
                mloc = fmaxf(mloc, ps.x);
            }
            if (r + 1 < M) {
                AS[(size_t)(r + 1) * HT + head] = ps.y;
                AD[(size_t)(r + 1) * HT + head] = pd.y;
                mloc = fmaxf(mloc, ps.y);
            }
        }
    }
    int lane = tid & 31;
#pragma unroll
    for (int o = 16; o > 0; o >>= 1)
        mloc = fmaxf(mloc, __shfl_xor_sync(0xffffffffu, mloc, o));
    if (lane == 0) smx[tid >> 5] = mloc;
    __syncthreads();
    if (tid == 0) {
        float m = smx[0];
#pragma unroll
        for (int i = 1; i < 8; i++) m = fmaxf(m, smx[i]);
        atomicMaxF(gMs, m);
    }
}

// ---------------- fused aggregate layer 1 (warp per dest, H=8, C=32) ----------------
__global__ void k_agg1(const float* __restrict__ as_, const float* __restrict__ ad_,
                       const float* __restrict__ xs, const float* __restrict__ bias,
                       float* __restrict__ hout, int n) {
    int w = (blockIdx.x * blockDim.x + threadIdx.x) >> 5;
    int lane = threadIdx.x & 31;
    if (w >= n) return;
    float Ms = g_Ms1;

    float as_h = 0.f, ad_h = 0.f, m = 0.f;
    if (lane < 8) {
        as_h = as_[w * 8 + lane];
        ad_h = ad_[w * 8 + lane];
        m = lrelu(Ms + ad_h);
    }
    float ex = (lane < 8) ? __expf(lrelu(as_h + ad_h) - m) : 0.f;
    float den = ex;

    int hsel = lane >> 3;
    float elo = __shfl_sync(0xffffffffu, ex, hsel);
    float ehi = __shfl_sync(0xffffffffu, ex, 4 + hsel);

    const float* xr = xs + (size_t)w * 256;
    float4 v0 = *(const float4*)&xr[4 * lane];
    float4 v1 = *(const float4*)&xr[128 + 4 * lane];
    float4 a0 = make_float4(v0.x * elo, v0.y * elo, v0.z * elo, v0.w * elo);
    float4 a1 = make_float4(v1.x * ehi, v1.y * ehi, v1.z * ehi, v1.w * ehi);

    int beg = g_ptr[w], end = g_ptr[w + 1];
    int e = beg;
    // 2x unrolled: two independent edge chains per iteration for MLP
    for (; e + 2 <= end; e += 2) {
        int sA = g_csr[e];
        int sB = g_csr[e + 1];
        float exA = 0.f, exB = 0.f;
        if (lane < 8) {
            float aA = lrelu(as_[sA * 8 + lane] + ad_h);
            float aB = lrelu(as_[sB * 8 + lane] + ad_h);
            exA = __expf(aA - m);
            exB = __expf(aB - m);
            den += exA + exB;
        }
        const float* urA = xs + (size_t)sA * 256;
        const float* urB = xs + (size_t)sB * 256;
        float4 uA0 = *(const float4*)&urA[4 * lane];
        float4 uA1 = *(const float4*)&urA[128 + 4 * lane];
        float4 uB0 = *(const float4*)&urB[4 * lane];
        float4 uB1 = *(const float4*)&urB[128 + 4 * lane];
        float fAlo = __shfl_sync(0xffffffffu, exA, hsel);
        float fAhi = __shfl_sync(0xffffffffu, exA, 4 + hsel);
        float fBlo = __shfl_sync(0xffffffffu, exB, hsel);
        float fBhi = __shfl_sync(0xffffffffu, exB, 4 + hsel);
        a0.x += uA0.x * fAlo; a0.y += uA0.y * fAlo; a0.z += uA0.z * fAlo; a0.w += uA0.w * fAlo;
        a1.x += uA1.x * fAhi; a1.y += uA1.y * fAhi; a1.z += uA1.z * fAhi; a1.w += uA1.w * fAhi;
        a0.x += uB0.x * fBlo; a0.y += uB0.y * fBlo; a0.z += uB0.z * fBlo; a0.w += uB0.w * fBlo;
        a1.x += uB1.x * fBhi; a1.y += uB1.y * fBhi; a1.z += uB1.z * fBhi; a1.w += uB1.w * fBhi;
    }
    if (e < end) {
        int s = g_csr[e];
        float exh = 0.f;
        if (lane < 8) {
            float a = lrelu(as_[s * 8 + lane] + ad_h);
            exh = __expf(a - m);
            den += exh;
        }
        float flo = __shfl_sync(0xffffffffu, exh, hsel);
        float fhi = __shfl_sync(0xffffffffu, exh, 4 + hsel);
        const float* ur = xs + (size_t)s * 256;
        float4 u0 = *(const float4*)&ur[4 * lane];
        float4 u1 = *(const float4*)&ur[128 + 4 * lane];
        a0.x += u0.x * flo; a0.y += u0.y * flo; a0.z += u0.z * flo; a0.w += u0.w * flo;
        a1.x += u1.x * fhi; a1.y += u1.y * fhi; a1.z += u1.z * fhi; a1.w += u1.w * fhi;
    }

    float dlo = __shfl_sync(0xffffffffu, den, hsel);
    float dhi = __shfl_sync(0xffffffffu, den, 4 + hsel);
    float rlo = 1.0f / dlo, rhi = 1.0f / dhi;
    float4 blo = *(const float4*)&bias[4 * lane];
    float4 bhi = *(const float4*)&bias[128 + 4 * lane];
    float4 o0, o1;
    o0.x = a0.x * rlo + blo.x; o0.y = a0.y * rlo + blo.y;
    o0.z = a0.z * rlo + blo.z; o0.w = a0.w * rlo + blo.w;
    o1.x = a1.x * rhi + bhi.x; o1.y = a1.y * rhi + bhi.y;
    o1.z = a1.z * rhi + bhi.z; o1.w = a1.w * rhi + bhi.w;
    o0.x = o0.x > 0.f ? o0.x : (expf(o0.x) - 1.f);
    o0.y = o0.y > 0.f ? o0.y : (expf(o0.y) - 1.f);
    o0.z = o0.z > 0.f ? o0.z : (expf(o0.z) - 1.f);
    o0.w = o0.w > 0.f ? o0.w : (expf(o0.w) - 1.f);
    o1.x = o1.x > 0.f ? o1.x : (expf(o1.x) - 1.f);
    o1.y = o1.y > 0.f ? o1.y : (expf(o1.y) - 1.f);
    o1.z = o1.z > 0.f ? o1.z : (expf(o1.z) - 1.f);
    o1.w = o1.w > 0.f ? o1.w : (expf(o1.w) - 1.f);
    float* hr = hout + (size_t)w * 256;
    *(float4*)&hr[4 * lane] = o0;
    *(float4*)&hr[128 + 4 * lane] = o1;
}

// ---------------- fused aggregate layer 2 (warp per dest, H=1, C=64) ----------------
__global__ void k_agg2(const float* __restrict__ as_, const float* __restrict__ ad_,
                       const float* __restrict__ xs, const float* __restrict__ bias,
                       float* __restrict__ out, int n) {
    int w = (blockIdx.x * blockDim.x + threadIdx.x) >> 5;
    int lane = threadIdx.x & 31;
    if (w >= n) return;
    float Ms = g_Ms2;
    float adv = ad_[w];
    float m = lrelu(Ms + adv);
    float ex = __expf(lrelu(as_[w] + adv) - m);
    float den = ex;
    float2 v = *(const float2*)&xs[(size_t)w * 64 + 2 * lane];
    float2 acc = make_float2(v.x * ex, v.y * ex);

    int beg = g_ptr[w], end = g_ptr[w + 1];
    int e = beg;
    for (; e + 2 <= end; e += 2) {
        int sA = g_csr[e];
        int sB = g_csr[e + 1];
        float aA = as_[sA];
        float aB = as_[sB];
        float2 uA = *(const float2*)&xs[(size_t)sA * 64 + 2 * lane];
        float2 uB = *(const float2*)&xs[(size_t)sB * 64 + 2 * lane];
        float exA = __expf(lrelu(aA + adv) - m);
        float exB = __expf(lrelu(aB + adv) - m);
        den += exA + exB;
        acc.x += uA.x * exA; acc.y += uA.y * exA;
        acc.x += uB.x * exB; acc.y += uB.y * exB;
    }
    if (e < end) {
        int s = g_csr[e];
        float exh = __expf(lrelu(as_[s] + adv) - m);
        den += exh;
        float2 u = *(const float2*)&xs[(size_t)s * 64 + 2 * lane];
        acc.x += u.x * exh;
        acc.y += u.y * exh;
    }
    float r = 1.0f / den;
    float2 b = *(const float2*)&bias[2 * lane];
    *(float2*)&out[(size_t)w * 64 + 2 * lane] =
        make_float2(acc.x * r + b.x, acc.y * r + b.y);
}

// ---------------- launcher ----------------
extern "C" void kernel_launch(void* const* d_in, const int* in_sizes, int n_in,
                              void* d_out, int out_size) {
    const float* x    = (const float*)d_in[0];
    const void*  ei   = d_in[1];
    const float* W1   = (const float*)d_in[2];
    const float* at1s = (const float*)d_in[3];
    const float* at1d = (const float*)d_in[4];
    const float* b1   = (const float*)d_in[5];
    const float* W2   = (const float*)d_in[6];
    const float* at2s = (const float*)d_in[7];
    const float* at2d = (const float*)d_in[8];
    const float* b2   = (const float*)d_in[9];
    float* out = (float*)d_out;

    int Nn = in_sizes[0] / 128;   // 50000
    int E  = in_sizes[1] / 2;     // 800000

    float *xs1, *h, *xs2, *as1, *ad1, *as2, *ad2, *Ms1, *Ms2;
    cudaGetSymbolAddress((void**)&xs1, g_xs1);
    cudaGetSymbolAddress((void**)&h,   g_h);
    cudaGetSymbolAddress((void**)&xs2, g_xs2);
    cudaGetSymbolAddress((void**)&as1, g_as1);
    cudaGetSymbolAddress((void**)&ad1, g_ad1);
    cudaGetSymbolAddress((void**)&as2, g_as2);
    cudaGetSymbolAddress((void**)&ad2, g_ad2);
    cudaGetSymbolAddress((void**)&Ms1, g_Ms1);
    cudaGetSymbolAddress((void**)&Ms2, g_Ms2);

    // one-time host-side resources (no device memory)
    static cudaStream_t s1 = nullptr;
    static cudaEvent_t evFork = nullptr, evJoin = nullptr;
    if (s1 == nullptr) {
        cudaStreamCreateWithFlags(&s1, cudaStreamNonBlocking);
        cudaEventCreateWithFlags(&evFork, cudaEventDisableTiming);
        cudaEventCreateWithFlags(&evJoin, cudaEventDisableTiming);
    }

    const int T = 256;
    int nodeBlocks = (Nn + T - 1) / T;
    int edgeBlocks = (E + T - 1) / T;
    int warpNodeBlocks = (Nn * 32 + T - 1) / T;
    int nsb = (Nn + SCAN_BLK - 1) / SCAN_BLK;

    // ---- fork: CSR build on side stream, GEMM1 on main stream ----
    cudaEventRecord(evFork, 0);
    cudaStreamWaitEvent(s1, evFork, 0);

    k_init<<<nodeBlocks, T, 0, s1>>>(Nn);
    k_detect<<<edgeBlocks, T, 0, s1>>>((const int*)ei, E);
    k_hist<<<edgeBlocks, T, 0, s1>>>(ei, E);
    k_scan1<<<nsb, SCAN_BLK, 0, s1>>>(Nn);
    k_scan2<<<1, 64, 0, s1>>>(nsb);
    k_scan3<<<nodeBlocks, T, 0, s1>>>(Nn, nsb);
    k_scatter<<<edgeBlocks, T, 0, s1>>>(ei, E);
    cudaEventRecord(evJoin, s1);

    // main stream: Ms init + GEMM1 with fused scores
    k_init_ms<<<1, 1>>>();
    {
        dim3 grid(256 / 64, (Nn + 127) / 128);
        k_gemm_sc<32, 8><<<grid, T>>>(x, W1, xs1, at1s, at1d, as1, ad1, Ms1,
                                      Nn, 256, 128);
    }

    // ---- join, then the serial tail ----
    cudaStreamWaitEvent(0, evJoin, 0);
    k_agg1<<<warpNodeBlocks, T>>>(as1, ad1, xs1, b1, h, Nn);

    {
        dim3 grid(1, (Nn + 127) / 128);
        k_gemm_sc<64, 1><<<grid, T>>>(h, W2, xs2, at2s, at2d, as2, ad2, Ms2,
                                      Nn, 64, 256);
    }
    k_agg2<<<warpNodeBlocks, T>>>(as2, ad2, xs2, b2, out, Nn);
}